// round 16
// baseline (speedup 1.0000x reference)
#include <cuda_runtime.h>
#include <cuda_bf16.h>
#include <cstdint>

// fast softplus for small |x| (here |x| <~ 2, far from exp overflow at 88):
__device__ __forceinline__ float softplus_f(float x) {
    return __logf(1.0f + __expf(x));
}

__device__ __forceinline__ uint32_t smem_u32(const void* p) {
    return (uint32_t)__cvta_generic_to_shared(p);
}

#define MBAR_INIT(addr, cnt) \
    asm volatile("mbarrier.init.shared.b64 [%0], %1;" :: "r"(addr), "r"(cnt) : "memory")
#define MBAR_EXPECT_TX(addr, bytes) \
    asm volatile("mbarrier.arrive.expect_tx.shared.b64 _, [%0], %1;" :: "r"(addr), "r"(bytes) : "memory")
#define BULK_G2S(dst_smem, src_gmem, nbytes, bar) \
    asm volatile("cp.async.bulk.shared::cta.global.mbarrier::complete_tx::bytes [%0], [%1], %2, [%3];" \
                 :: "r"(dst_smem), "l"(src_gmem), "r"(nbytes), "r"(bar) : "memory")

__device__ __forceinline__ void mbar_wait_parity(uint32_t bar, uint32_t parity) {
    uint32_t done;
    asm volatile(
        "{\n\t.reg .pred p;\n\t"
        "mbarrier.try_wait.parity.acquire.cta.shared::cta.b64 p, [%1], %2;\n\t"
        "selp.b32 %0, 1, 0, p;\n\t}"
        : "=r"(done) : "r"(bar), "r"(parity) : "memory");
    while (!done) {
        asm volatile(
            "{\n\t.reg .pred p;\n\t"
            "mbarrier.try_wait.parity.acquire.cta.shared::cta.b64 p, [%1], %2, 0x989680;\n\t"
            "selp.b32 %0, 1, 0, p;\n\t}"
            : "=r"(done) : "r"(bar), "r"(parity) : "memory");
    }
}

// One CTA per batch row, 7 CTAs/SM, single wave. Two-phase chunk pipeline:
// Phase A: conflict-free LDS; thread handling element e reads ts=xb[e].x and
//   the FULL predecessor xb[e-1], computes f(e-1) (each f computed exactly
//   once chip-wide), incr[e] = (ts - ts_{e-1})*f_{e-1}. NO shuffles, no
//   divergent lane-0 path. Chunk-boundary (ts,f) via one-thread bnd write.
// Phase B: conflict-free LDS.128 of incr, prefix + block scan, STG.128.
// TMA refill issued right after the A->B barrier so it overlaps phase B.
template <int NTHREADS, int CELEMS, int RING>
__global__ __launch_bounds__(NTHREADS, 7)
void soc_kernel(const float4* __restrict__ X,       // (B, T, 4)
                const float*  __restrict__ SC,      // (B, 4)
                const float*  __restrict__ W1i, const float* __restrict__ b1i,
                const float*  __restrict__ W2i, const float* __restrict__ b2i,
                const float*  __restrict__ W1e, const float* __restrict__ b1e,
                const float*  __restrict__ W2e, const float* __restrict__ b2e,
                float* __restrict__ out,            // (B, T)
                int T)
{
    extern __shared__ __align__(128) float4 xbuf[];    // RING*CELEMS float4 + CELEMS floats
    float* incr = reinterpret_cast<float*>(xbuf + RING * CELEMS);
    __shared__ __align__(8) uint64_t mbar[RING];
    __shared__ float warp_tot[2][32];                  // double-buffered
    __shared__ float2 bnd[2];                          // (ts, f) carry, double-buffered

    const int b    = blockIdx.x;
    const int tid  = threadIdx.x;
    const int lane = tid & 31;
    const int warp = tid >> 5;
    constexpr int NW = NTHREADS / 32;                  // 7
    constexpr int NJ = CELEMS / NTHREADS;              // 4
    const unsigned FULL = 0xFFFFFFFFu;
    const long long rowbase = (long long)b * (long long)T;
    const int nchunks = (T + CELEMS - 1) / CELEMS;

    if (tid == 0) {
        #pragma unroll
        for (int r = 0; r < RING; r++)
            MBAR_INIT(smem_u32(&mbar[r]), 1);
    }
    __syncthreads();

    // prime the ring
    if (tid == 0) {
        const int prime = (nchunks < RING) ? nchunks : RING;
        for (int c = 0; c < prime; c++) {
            const int lim = min(CELEMS, T - c * CELEMS);
            const uint32_t nbytes = (uint32_t)lim * 16u;
            const uint32_t bar = smem_u32(&mbar[c]);
            MBAR_EXPECT_TX(bar, nbytes);
            BULK_G2S(smem_u32(&xbuf[c * CELEMS]),
                     (const void*)(X + rowbase + (long long)c * CELEMS),
                     nbytes, bar);
        }
    }

    // Per-batch scalars (overlaps with TMA flight)
    const float w1e0 = W1e[0], w1e1 = W1e[1];
    const float be1  = b1e[0];
    const float scale = SC[b * 4 + 1] / (3600.0f * SC[b * 4 + 0]);
    const float A  = scale * (1.0f + b2e[0]);  // f = I * (A + B*h)
    const float Bc = scale * W2e[0];

    float base = 0.0f;   // SOC_init + running cumsum carry (set at c==0)

    for (int c = 0; c < nchunks; c++) {
        const int slot = c % RING;
        mbar_wait_parity(smem_u32(&mbar[slot]), (uint32_t)((c / RING) & 1));

        const float4* xb = &xbuf[slot * CELEMS];
        const int lim = min(CELEMS, T - c * CELEMS);
        const int cb = c & 1;

        if (c == 0) {
            // SOC_init from t=0 features (broadcast LDS); exact softplus form
            float4 x0 = xb[0];
            float z0 = x0.y * W1i[0] + x0.z * W1i[1] + x0.w * W1i[2]
                     + SC[b * 4 + 2] * W1i[3] + b1i[0];
            float h0 = fmaxf(z0, 0.0f) + __logf(1.0f + __expf(-fabsf(z0)));
            base = SC[b * 4 + 3] * (1.0f + (h0 * W2i[0] + b2i[0]));
        }

        // boundary carry for NEXT chunk: one thread computes f(last element)
        if (tid == NTHREADS - 1) {
            float4 vl = xb[lim - 1];
            float hl = softplus_f(fmaf(vl.y, w1e0, fmaf(vl.z, w1e1, be1)));
            bnd[cb ^ 1] = make_float2(vl.x, vl.y * fmaf(hl, Bc, A));
        }

        // ---- Phase A: no shuffles; predecessor read directly from SMEM ----
        #pragma unroll
        for (int j = 0; j < NJ; j++) {
            const int e = j * NTHREADS + tid;
            if (e < lim) {
                float ic;
                if (e > 0) {
                    float ts = xb[e].x;                 // LDS.32, conflict-free
                    float4 vp = xb[e - 1];              // LDS.128, conflict-free
                    float hp = softplus_f(fmaf(vp.y, w1e0, fmaf(vp.z, w1e1, be1)));
                    float pf = vp.y * fmaf(hp, Bc, A);
                    ic = (ts - vp.x) * pf;
                } else if (c > 0) {
                    float2 bc = bnd[cb];                // prev chunk's (ts,f)
                    ic = (xb[0].x - bc.x) * bc.y;
                } else {
                    ic = 0.0f;                          // global t==0
                }
                incr[e] = ic;                           // coalesced STS.32
            }
        }
        __syncthreads();                                // barrier 1: incr ready, xb consumed

        // refill the freed slot NOW (overlaps phase B)
        if (tid == NTHREADS - 1 && c + RING < nchunks) {
            const int cn = c + RING;
            const int nlim = min(CELEMS, T - cn * CELEMS);
            const uint32_t nbytes = (uint32_t)nlim * 16u;
            const uint32_t bar = smem_u32(&mbar[slot]);
            MBAR_EXPECT_TX(bar, nbytes);
            BULK_G2S(smem_u32(&xbuf[slot * CELEMS]),
                     (const void*)(X + rowbase + (long long)cn * CELEMS),
                     nbytes, bar);
        }

        // ---- Phase B: conflict-free LDS.128 of incr, prefix + block scan ----
        const int s = tid * 4;
        float p0 = 0.f, p1 = 0.f, p2 = 0.f, run = 0.f;
        if (s + 3 < lim) {
            float4 iv = *reinterpret_cast<const float4*>(incr + s);  // 16B stride
            p0 = iv.x;
            p1 = p0 + iv.y;
            p2 = p1 + iv.z;
            run = p2 + iv.w;
        } else if (s < lim) {
            float acc = 0.f;
            float pv[4] = {0.f, 0.f, 0.f, 0.f};
            for (int j = 0; j < 4; j++) {
                if (s + j < lim) { acc += incr[s + j]; pv[j] = acc; }
            }
            p0 = pv[0]; p1 = pv[1]; p2 = pv[2]; run = acc;
        }

        // warp-inclusive scan of per-thread totals
        float v = run;
        #pragma unroll
        for (int d = 1; d < 32; d <<= 1) {
            float o = __shfl_up_sync(FULL, v, d);
            if (lane >= d) v += o;
        }
        if (lane == 31) warp_tot[cb][warp] = v;
        __syncthreads();                                // barrier 2

        // every warp redundantly scans the NW warp totals (no 3rd sync)
        float w = (lane < NW) ? warp_tot[cb][lane] : 0.0f;
        #pragma unroll
        for (int d = 1; d < 8; d <<= 1) {               // covers NW=7
            float o = __shfl_up_sync(FULL, w, d);
            if (lane >= d) w += o;
        }
        const float warp_off = (warp > 0) ? __shfl_sync(FULL, w, warp - 1) : 0.0f;
        const float total    = __shfl_sync(FULL, w, NW - 1);

        const float excl = base + warp_off + (v - run);

        // ---- write out (STG.128) ----
        if (s + 3 < lim) {
            float4 ov;
            ov.x = excl + p0;
            ov.y = excl + p1;
            ov.z = excl + p2;
            ov.w = excl + run;
            *reinterpret_cast<float4*>(out + rowbase + c * CELEMS + s) = ov;
        } else if (s < lim) {
            const float pv[4] = {p0, p1, p2, run};
            for (int j = 0; j < 4; j++)
                if (s + j < lim) out[rowbase + c * CELEMS + s + j] = excl + pv[j];
        }

        base += total;
    }
}

extern "C" void kernel_launch(void* const* d_in, const int* in_sizes, int n_in,
                              void* d_out, int out_size)
{
    const float4* X  = (const float4*)d_in[0];   // (B, T, 4) fp32
    const float* SC  = (const float*)d_in[1];    // (B, 4)
    const float* W1i = (const float*)d_in[2];
    const float* b1i = (const float*)d_in[3];
    const float* W2i = (const float*)d_in[4];
    const float* b2i = (const float*)d_in[5];
    const float* W1e = (const float*)d_in[6];
    const float* b1e = (const float*)d_in[7];
    const float* W2e = (const float*)d_in[8];
    const float* b2e = (const float*)d_in[9];
    float* out = (float*)d_out;

    const int B = in_sizes[1] / 4;               // SC is (B,4)
    const int T = in_sizes[0] / (B * 4);         // X is (B,T,4)

    constexpr int NTH = 224, CEL = 896, RING = 2;
    const int smem_bytes = RING * CEL * 16 + CEL * 4;  // 28.7KB x + 3.5KB incr
    static bool attr_set = false;
    if (!attr_set) {
        cudaFuncSetAttribute(soc_kernel<NTH, CEL, RING>,
                             cudaFuncAttributeMaxDynamicSharedMemorySize, smem_bytes);
        attr_set = true;
    }
    soc_kernel<NTH, CEL, RING><<<B, NTH, smem_bytes>>>(
        X, SC, W1i, b1i, W2i, b2i, W1e, b1e, W2e, b2e, out, T);
}

// round 17
// speedup vs baseline: 1.0686x; 1.0686x over previous
#include <cuda_runtime.h>
#include <cuda_bf16.h>
#include <cstdint>

// fast softplus for small |x| (here |x| <~ 2, far from exp overflow at 88):
__device__ __forceinline__ float softplus_f(float x) {
    return __logf(1.0f + __expf(x));
}

__device__ __forceinline__ uint32_t smem_u32(const void* p) {
    return (uint32_t)__cvta_generic_to_shared(p);
}

#define MBAR_INIT(addr, cnt) \
    asm volatile("mbarrier.init.shared.b64 [%0], %1;" :: "r"(addr), "r"(cnt) : "memory")
#define MBAR_EXPECT_TX(addr, bytes) \
    asm volatile("mbarrier.arrive.expect_tx.shared.b64 _, [%0], %1;" :: "r"(addr), "r"(bytes) : "memory")
#define BULK_G2S(dst_smem, src_gmem, nbytes, bar) \
    asm volatile("cp.async.bulk.shared::cta.global.mbarrier::complete_tx::bytes [%0], [%1], %2, [%3];" \
                 :: "r"(dst_smem), "l"(src_gmem), "r"(nbytes), "r"(bar) : "memory")

__device__ __forceinline__ void mbar_wait_parity(uint32_t bar, uint32_t parity) {
    uint32_t done;
    asm volatile(
        "{\n\t.reg .pred p;\n\t"
        "mbarrier.try_wait.parity.acquire.cta.shared::cta.b64 p, [%1], %2;\n\t"
        "selp.b32 %0, 1, 0, p;\n\t}"
        : "=r"(done) : "r"(bar), "r"(parity) : "memory");
    while (!done) {
        asm volatile(
            "{\n\t.reg .pred p;\n\t"
            "mbarrier.try_wait.parity.acquire.cta.shared::cta.b64 p, [%1], %2, 0x989680;\n\t"
            "selp.b32 %0, 1, 0, p;\n\t}"
            : "=r"(done) : "r"(bar), "r"(parity) : "memory");
    }
}

// One CTA per batch row, 8 CTAs/SM (27.6KB smem each), single wave.
// Two-phase chunk pipeline (R15 structure):
// Phase A: coalesced (conflict-free) LDS of x, compute incr[e] with shfl
//   predecessor exchange, coalesced STS.
// Phase B: conflict-free LDS.128 of incr (16B lane stride), prefix + block
//   scan, STG.128. TMA refill issued right after the A->B barrier.
template <int NTHREADS, int CELEMS, int RING>
__global__ __launch_bounds__(NTHREADS, 8)
void soc_kernel(const float4* __restrict__ X,       // (B, T, 4)
                const float*  __restrict__ SC,      // (B, 4)
                const float*  __restrict__ W1i, const float* __restrict__ b1i,
                const float*  __restrict__ W2i, const float* __restrict__ b2i,
                const float*  __restrict__ W1e, const float* __restrict__ b1e,
                const float*  __restrict__ W2e, const float* __restrict__ b2e,
                float* __restrict__ out,            // (B, T)
                int T)
{
    extern __shared__ __align__(128) float4 xbuf[];    // RING*CELEMS float4 + CELEMS floats
    float* incr = reinterpret_cast<float*>(xbuf + RING * CELEMS);
    __shared__ __align__(8) uint64_t mbar[RING];
    __shared__ float warp_tot[2][32];                  // double-buffered
    __shared__ float2 bnd[2];                          // (ts, f) carry, double-buffered

    const int b    = blockIdx.x;
    const int tid  = threadIdx.x;
    const int lane = tid & 31;
    const int warp = tid >> 5;
    constexpr int NW = NTHREADS / 32;                  // 6
    constexpr int NJ = CELEMS / NTHREADS;              // 4
    const unsigned FULL = 0xFFFFFFFFu;
    const long long rowbase = (long long)b * (long long)T;
    const int nchunks = (T + CELEMS - 1) / CELEMS;

    if (tid == 0) {
        #pragma unroll
        for (int r = 0; r < RING; r++)
            MBAR_INIT(smem_u32(&mbar[r]), 1);
    }
    __syncthreads();

    // prime the ring
    if (tid == 0) {
        const int prime = (nchunks < RING) ? nchunks : RING;
        for (int c = 0; c < prime; c++) {
            const int lim = min(CELEMS, T - c * CELEMS);
            const uint32_t nbytes = (uint32_t)lim * 16u;
            const uint32_t bar = smem_u32(&mbar[c]);
            MBAR_EXPECT_TX(bar, nbytes);
            BULK_G2S(smem_u32(&xbuf[c * CELEMS]),
                     (const void*)(X + rowbase + (long long)c * CELEMS),
                     nbytes, bar);
        }
    }

    // Per-batch scalars (overlaps with TMA flight)
    const float w1e0 = W1e[0], w1e1 = W1e[1];
    const float be1  = b1e[0];
    const float scale = SC[b * 4 + 1] / (3600.0f * SC[b * 4 + 0]);
    const float A  = scale * (1.0f + b2e[0]);  // f = I * (A + B*h)
    const float Bc = scale * W2e[0];

    float base = 0.0f;   // SOC_init + running cumsum carry (set at c==0)

    for (int c = 0; c < nchunks; c++) {
        const int slot = c % RING;
        mbar_wait_parity(smem_u32(&mbar[slot]), (uint32_t)((c / RING) & 1));

        const float4* xb = &xbuf[slot * CELEMS];
        const int lim = min(CELEMS, T - c * CELEMS);
        const int cb = c & 1;

        if (c == 0) {
            // SOC_init from t=0 features (broadcast LDS); exact softplus form
            float4 x0 = xb[0];
            float z0 = x0.y * W1i[0] + x0.z * W1i[1] + x0.w * W1i[2]
                     + SC[b * 4 + 2] * W1i[3] + b1i[0];
            float h0 = fmaxf(z0, 0.0f) + __logf(1.0f + __expf(-fabsf(z0)));
            base = SC[b * 4 + 3] * (1.0f + (h0 * W2i[0] + b2i[0]));
        }

        // ---- Phase A: coalesced LDS, compute incr, coalesced STS ----
        #pragma unroll
        for (int j = 0; j < NJ; j++) {
            const int e = j * NTHREADS + tid;
            if (e < lim) {
                float4 v = xb[e];                       // conflict-free LDS.128
                float ts = v.x;
                float h  = softplus_f(fmaf(v.y, w1e0, fmaf(v.z, w1e1, be1)));
                float f  = v.y * fmaf(h, Bc, A);

                float pts = __shfl_up_sync(FULL, ts, 1);
                float pf  = __shfl_up_sync(FULL, f, 1);
                if (lane == 0) {
                    if (e > 0) {                        // warp boundary: recompute
                        float4 vp = xb[e - 1];
                        float hp = softplus_f(fmaf(vp.y, w1e0, fmaf(vp.z, w1e1, be1)));
                        pts = vp.x;
                        pf  = vp.y * fmaf(hp, Bc, A);
                    } else if (c > 0) {                 // chunk boundary carry
                        float2 bc = bnd[cb];
                        pts = bc.x; pf = bc.y;
                    }
                }
                float ic = (c == 0 && e == 0) ? 0.0f : (ts - pts) * pf;
                incr[e] = ic;                           // coalesced STS.32
                if (e == lim - 1) bnd[cb ^ 1] = make_float2(ts, f);
            }
        }
        __syncthreads();                                // barrier 1: incr ready, xb consumed

        // refill the freed slot NOW (overlaps phase B)
        if (tid == NTHREADS - 1 && c + RING < nchunks) {
            const int cn = c + RING;
            const int nlim = min(CELEMS, T - cn * CELEMS);
            const uint32_t nbytes = (uint32_t)nlim * 16u;
            const uint32_t bar = smem_u32(&mbar[slot]);
            MBAR_EXPECT_TX(bar, nbytes);
            BULK_G2S(smem_u32(&xbuf[slot * CELEMS]),
                     (const void*)(X + rowbase + (long long)cn * CELEMS),
                     nbytes, bar);
        }

        // ---- Phase B: conflict-free LDS.128 of incr, prefix + block scan ----
        const int s = tid * 4;
        float p0 = 0.f, p1 = 0.f, p2 = 0.f, run = 0.f;
        if (s + 3 < lim) {
            float4 iv = *reinterpret_cast<const float4*>(incr + s);  // 16B stride
            p0 = iv.x;
            p1 = p0 + iv.y;
            p2 = p1 + iv.z;
            run = p2 + iv.w;
        } else if (s < lim) {
            float acc = 0.f;
            float pv[4] = {0.f, 0.f, 0.f, 0.f};
            for (int j = 0; j < 4; j++) {
                if (s + j < lim) { acc += incr[s + j]; pv[j] = acc; }
            }
            p0 = pv[0]; p1 = pv[1]; p2 = pv[2]; run = acc;
        }

        // warp-inclusive scan of per-thread totals
        float v = run;
        #pragma unroll
        for (int d = 1; d < 32; d <<= 1) {
            float o = __shfl_up_sync(FULL, v, d);
            if (lane >= d) v += o;
        }
        if (lane == 31) warp_tot[cb][warp] = v;
        __syncthreads();                                // barrier 2

        // every warp redundantly scans the NW warp totals (no 3rd sync)
        float w = (lane < NW) ? warp_tot[cb][lane] : 0.0f;
        #pragma unroll
        for (int d = 1; d < 8; d <<= 1) {               // covers NW=6
            float o = __shfl_up_sync(FULL, w, d);
            if (lane >= d) w += o;
        }
        const float warp_off = (warp > 0) ? __shfl_sync(FULL, w, warp - 1) : 0.0f;
        const float total    = __shfl_sync(FULL, w, NW - 1);

        const float excl = base + warp_off + (v - run);

        // ---- write out (STG.128) ----
        if (s + 3 < lim) {
            float4 ov;
            ov.x = excl + p0;
            ov.y = excl + p1;
            ov.z = excl + p2;
            ov.w = excl + run;
            *reinterpret_cast<float4*>(out + rowbase + c * CELEMS + s) = ov;
        } else if (s < lim) {
            const float pv[4] = {p0, p1, p2, run};
            for (int j = 0; j < 4; j++)
                if (s + j < lim) out[rowbase + c * CELEMS + s + j] = excl + pv[j];
        }

        base += total;
    }
}

extern "C" void kernel_launch(void* const* d_in, const int* in_sizes, int n_in,
                              void* d_out, int out_size)
{
    const float4* X  = (const float4*)d_in[0];   // (B, T, 4) fp32
    const float* SC  = (const float*)d_in[1];    // (B, 4)
    const float* W1i = (const float*)d_in[2];
    const float* b1i = (const float*)d_in[3];
    const float* W2i = (const float*)d_in[4];
    const float* b2i = (const float*)d_in[5];
    const float* W1e = (const float*)d_in[6];
    const float* b1e = (const float*)d_in[7];
    const float* W2e = (const float*)d_in[8];
    const float* b2e = (const float*)d_in[9];
    float* out = (float*)d_out;

    const int B = in_sizes[1] / 4;               // SC is (B,4)
    const int T = in_sizes[0] / (B * 4);         // X is (B,T,4)

    constexpr int NTH = 192, CEL = 768, RING = 2;
    const int smem_bytes = RING * CEL * 16 + CEL * 4;  // 24KB x + 3KB incr = 27.6KB
    static bool attr_set = false;
    if (!attr_set) {
        cudaFuncSetAttribute(soc_kernel<NTH, CEL, RING>,
                             cudaFuncAttributeMaxDynamicSharedMemorySize, smem_bytes);
        attr_set = true;
    }
    soc_kernel<NTH, CEL, RING><<<B, NTH, smem_bytes>>>(
        X, SC, W1i, b1i, W2i, b2i, W1e, b1e, W2e, b2e, out, T);
}